// round 10
// baseline (speedup 1.0000x reference)
#include <cuda_runtime.h>
#include <cuda_fp16.h>
#include <math.h>

#define N_NODES 50000
#define FDIM    256
#define NCLS    40
#define NPAD    64
#define MAX_E   1700000
#define SP      40          // smem row stride in halves (conflict-free frags)
#define CHUNK_ROWS 12544    // 98 * 128
#define NCHUNK  4

// Scratch (device globals only — no runtime allocation)
__device__ __half g_Y1h[(size_t)N_NODES * FDIM];   // conv1 GEMM out
__device__ __half g_Y2h[(size_t)N_NODES * FDIM];   // conv2 GEMM out
__device__ __half g_h1h[(size_t)N_NODES * FDIM];   // conv1 aggregate
__device__ __half g_h2h[(size_t)N_NODES * FDIM];   // conv2 aggregate
__device__ __half g_w1t[FDIM * FDIM];              // W1^T fp16 [n][k]
__device__ __half g_w2t[FDIM * FDIM];              // W2^T fp16 [n][k]
__device__ __half g_wfct[NPAD * FDIM];             // Wfc^T fp16 [n][k], padded
__device__ float  g_bfcp[NPAD];
__device__ float  g_logits[(size_t)N_NODES * NCLS];
__device__ int    g_sortedSrc[MAX_E];
__device__ int    g_rowStart[N_NODES + 1];
__device__ int    g_deg[N_NODES];
__device__ int    g_cursor[N_NODES];
// PvT CSR (row-sorted)
__device__ int    g_pdeg[N_NODES];
__device__ int    g_pcursor[N_NODES];
__device__ int    g_prowStart[N_NODES + 1];
__device__ int    g_pcolS[N_NODES + 64];
__device__ float  g_pvalS[N_NODES + 64];

// ---------------------------------------------------------------------------
// Weight converts
// ---------------------------------------------------------------------------
__global__ __launch_bounds__(256) void wconv_kernel(
    const float* __restrict__ W, __half* __restrict__ Wt)
{
    int n = blockIdx.x;
    int k = threadIdx.x;
    Wt[n * FDIM + k] = __float2half(__ldg(W + k * FDIM + n));
}

__global__ __launch_bounds__(256) void wfc_conv_kernel(
    const float* __restrict__ Wfc, __half* __restrict__ Wt)
{
    int n = blockIdx.x;           // 0..63
    int k = threadIdx.x;
    Wt[n * FDIM + k] = (n < NCLS) ? __float2half(__ldg(Wfc + k * NCLS + n))
                                  : __float2half(0.0f);
}

__global__ __launch_bounds__(64) void bfc_pad_kernel(
    const float* __restrict__ bfc, float* __restrict__ bp)
{
    int i = threadIdx.x;
    bp[i] = (i < NCLS) ? __ldg(bfc + i) : 0.0f;
}

// ---------------------------------------------------------------------------
// CSR build (generic over bucket histogram of size N_NODES)
// ---------------------------------------------------------------------------
__global__ __launch_bounds__(256) void zero2_i32(int* __restrict__ a,
                                                 int* __restrict__ b, int n)
{
    int i = blockIdx.x * blockDim.x + threadIdx.x;
    if (i < n) { a[i] = 0; b[i] = 0; }
}

// 4 elements per thread for MLP
__global__ __launch_bounds__(256) void hist_kernel(
    const int* __restrict__ dst, int* __restrict__ deg, int E)
{
    int base = (blockIdx.x * blockDim.x + threadIdx.x) * 4;
    if (base + 4 <= E) {
        int4 d = *(const int4*)(dst + base);
        atomicAdd(&deg[d.x], 1);
        atomicAdd(&deg[d.y], 1);
        atomicAdd(&deg[d.z], 1);
        atomicAdd(&deg[d.w], 1);
    } else {
        for (int i = base; i < E; i++) atomicAdd(&deg[__ldg(dst + i)], 1);
    }
}

__global__ __launch_bounds__(1024) void scan_kernel(
    const int* __restrict__ deg, int* __restrict__ rowStart)
{
    __shared__ int sums[1024];
    const int tid = threadIdx.x;
    const int CH  = (N_NODES + 1023) / 1024;
    const int base = tid * CH;
    int s = 0;
    for (int i = 0; i < CH; i++) {
        int idx = base + i;
        if (idx < N_NODES) s += deg[idx];
    }
    sums[tid] = s;
    __syncthreads();
    for (int off = 1; off < 1024; off <<= 1) {
        int v = (tid >= off) ? sums[tid - off] : 0;
        __syncthreads();
        sums[tid] += v;
        __syncthreads();
    }
    int run = sums[tid] - s;
    for (int i = 0; i < CH; i++) {
        int idx = base + i;
        if (idx < N_NODES) { rowStart[idx] = run; run += deg[idx]; }
    }
    if (tid == 1023) rowStart[N_NODES] = run;
}

// 4 edges per thread for MLP
__global__ __launch_bounds__(256) void scatter_kernel(
    const int* __restrict__ src, const int* __restrict__ dst,
    const int* __restrict__ rowStart, int* __restrict__ cursor,
    int* __restrict__ sortedSrc, int E)
{
    int base = (blockIdx.x * blockDim.x + threadIdx.x) * 4;
    if (base + 4 <= E) {
        int4 d = *(const int4*)(dst + base);
        int4 s = *(const int4*)(src + base);
        int r0 = __ldg(rowStart + d.x);
        int r1 = __ldg(rowStart + d.y);
        int r2 = __ldg(rowStart + d.z);
        int r3 = __ldg(rowStart + d.w);
        int p0 = r0 + atomicAdd(&cursor[d.x], 1);
        int p1 = r1 + atomicAdd(&cursor[d.y], 1);
        int p2 = r2 + atomicAdd(&cursor[d.z], 1);
        int p3 = r3 + atomicAdd(&cursor[d.w], 1);
        sortedSrc[p0] = s.x;
        sortedSrc[p1] = s.y;
        sortedSrc[p2] = s.z;
        sortedSrc[p3] = s.w;
    } else {
        for (int i = base; i < E; i++) {
            int d = __ldg(dst + i);
            int pos = __ldg(rowStart + d) + atomicAdd(&cursor[d], 1);
            sortedSrc[pos] = __ldg(src + i);
        }
    }
}

// PvT scatter: carries (col, val) into row-sorted order
__global__ __launch_bounds__(256) void pvt_scatter_kernel(
    const int* __restrict__ prow, const int* __restrict__ pcol,
    const float* __restrict__ pval, const int* __restrict__ rowStart,
    int* __restrict__ cursor, int* __restrict__ colS,
    float* __restrict__ valS, int nnz)
{
    int i = blockIdx.x * blockDim.x + threadIdx.x;
    if (i >= nnz) return;
    int r = __ldg(prow + i);
    int pos = __ldg(rowStart + r) + atomicAdd(&cursor[r], 1);
    colS[pos] = __ldg(pcol + i);
    valS[pos] = __ldg(pval + i);
}

// ---------------------------------------------------------------------------
// Tensor-core GEMM: Y = half(relu(A[M,256] @ W[256,256] + bias)).
// ---------------------------------------------------------------------------
__device__ __forceinline__ void mma_16816(float c[4], const unsigned a[4],
                                          const unsigned b[2])
{
    asm volatile(
        "mma.sync.aligned.m16n8k16.row.col.f32.f16.f16.f32 "
        "{%0,%1,%2,%3}, {%4,%5,%6,%7}, {%8,%9}, {%0,%1,%2,%3};\n"
        : "+f"(c[0]), "+f"(c[1]), "+f"(c[2]), "+f"(c[3])
        : "r"(a[0]), "r"(a[1]), "r"(a[2]), "r"(a[3]), "r"(b[0]), "r"(b[1]));
}

template <bool A_FP32>
__global__ __launch_bounds__(256, 2) void gemm_mma(
    const void* __restrict__ Av, const __half* __restrict__ Wt,
    const float* __restrict__ bias, __half* __restrict__ Y, int rowOff)
{
    __shared__ __half As[128 * SP];
    __shared__ __half Bs[128 * SP];

    const int tid   = threadIdx.x;
    const int wid   = tid >> 5;
    const int lane  = tid & 31;
    const int gid   = lane >> 2;
    const int tig   = lane & 3;
    const int warp_m = wid & 3;
    const int warp_n = wid >> 2;
    const int rowBase = rowOff + blockIdx.y * 128;
    const int colBase = blockIdx.x * 128;

    float acc[2][8][4];
#pragma unroll
    for (int mf = 0; mf < 2; mf++)
#pragma unroll
        for (int nf = 0; nf < 8; nf++)
#pragma unroll
            for (int j = 0; j < 4; j++) acc[mf][nf][j] = 0.0f;

    for (int k0 = 0; k0 < FDIM; k0 += 32) {
#pragma unroll
        for (int i = 0; i < 2; i++) {
            int idx = tid + i * 256;
            int r   = idx >> 2;
            int cg  = idx & 3;
            int gr  = rowBase + r;
            uint4 va;
            if (A_FP32) {
                float4 f0 = make_float4(0.f, 0.f, 0.f, 0.f);
                float4 f1 = make_float4(0.f, 0.f, 0.f, 0.f);
                if (gr < N_NODES) {
                    const float* ap = (const float*)Av + (size_t)gr * FDIM + k0 + cg * 8;
                    f0 = *(const float4*)ap;
                    f1 = *(const float4*)(ap + 4);
                }
                __half2 h0 = __floats2half2_rn(f0.x, f0.y);
                __half2 h1 = __floats2half2_rn(f0.z, f0.w);
                __half2 h2 = __floats2half2_rn(f1.x, f1.y);
                __half2 h3 = __floats2half2_rn(f1.z, f1.w);
                va = make_uint4(*(unsigned*)&h0, *(unsigned*)&h1,
                                *(unsigned*)&h2, *(unsigned*)&h3);
            } else {
                va = make_uint4(0u, 0u, 0u, 0u);
                if (gr < N_NODES)
                    va = *(const uint4*)((const __half*)Av + (size_t)gr * FDIM + k0 + cg * 8);
            }
            *(uint4*)&As[r * SP + cg * 8] = va;
            uint4 vb = *(const uint4*)(Wt + (size_t)(colBase + r) * FDIM + k0 + cg * 8);
            *(uint4*)&Bs[r * SP + cg * 8] = vb;
        }
        __syncthreads();

#pragma unroll
        for (int ks = 0; ks < 2; ks++) {
            const int kk = ks * 16 + tig * 2;
            unsigned af[2][4];
#pragma unroll
            for (int mf = 0; mf < 2; mf++) {
                int r0 = warp_m * 32 + mf * 16 + gid;
                af[mf][0] = *(const unsigned*)&As[(r0    ) * SP + kk];
                af[mf][1] = *(const unsigned*)&As[(r0 + 8) * SP + kk];
                af[mf][2] = *(const unsigned*)&As[(r0    ) * SP + kk + 8];
                af[mf][3] = *(const unsigned*)&As[(r0 + 8) * SP + kk + 8];
            }
#pragma unroll
            for (int nf = 0; nf < 8; nf++) {
                int c0 = warp_n * 64 + nf * 8 + gid;
                unsigned bf[2];
                bf[0] = *(const unsigned*)&Bs[c0 * SP + kk];
                bf[1] = *(const unsigned*)&Bs[c0 * SP + kk + 8];
                mma_16816(acc[0][nf], af[0], bf);
                mma_16816(acc[1][nf], af[1], bf);
            }
        }
        __syncthreads();
    }

    float2 bv[8];
#pragma unroll
    for (int nf = 0; nf < 8; nf++)
        bv[nf] = *(const float2*)(bias + colBase + warp_n * 64 + nf * 8 + tig * 2);

#pragma unroll
    for (int mf = 0; mf < 2; mf++) {
        int gr0 = rowBase + warp_m * 32 + mf * 16 + gid;
        int gr1 = gr0 + 8;
#pragma unroll
        for (int nf = 0; nf < 8; nf++) {
            int col = colBase + warp_n * 64 + nf * 8 + tig * 2;
            if (gr0 < N_NODES) {
                __half2 h = __floats2half2_rn(
                    fmaxf(acc[mf][nf][0] + bv[nf].x, 0.f),
                    fmaxf(acc[mf][nf][1] + bv[nf].y, 0.f));
                *(__half2*)(Y + (size_t)gr0 * FDIM + col) = h;
            }
            if (gr1 < N_NODES) {
                __half2 h = __floats2half2_rn(
                    fmaxf(acc[mf][nf][2] + bv[nf].x, 0.f),
                    fmaxf(acc[mf][nf][3] + bv[nf].y, 0.f));
                *(__half2*)(Y + (size_t)gr1 * FDIM + col) = h;
            }
        }
    }
}

// ---------------------------------------------------------------------------
// FC via tensor cores: logits[N,40] = h2[N,256](fp16) @ WfcT + bfc (fp32 out).
// ---------------------------------------------------------------------------
__global__ __launch_bounds__(256, 2) void fc_mma(
    const __half* __restrict__ A, const __half* __restrict__ Wt,
    const float* __restrict__ bias, float* __restrict__ L, int rowOff)
{
    __shared__ __half As[128 * SP];
    __shared__ __half Bs[64 * SP];

    const int tid  = threadIdx.x;
    const int wid  = tid >> 5;
    const int lane = tid & 31;
    const int gid  = lane >> 2;
    const int tig  = lane & 3;
    const int rowBase = rowOff + blockIdx.y * 128;

    float acc[8][4];
#pragma unroll
    for (int nf = 0; nf < 8; nf++)
#pragma unroll
        for (int j = 0; j < 4; j++) acc[nf][j] = 0.0f;

    for (int k0 = 0; k0 < FDIM; k0 += 32) {
#pragma unroll
        for (int i = 0; i < 2; i++) {
            int idx = tid + i * 256;
            int r   = idx >> 2;
            int cg  = idx & 3;
            int gr  = rowBase + r;
            uint4 va = make_uint4(0u, 0u, 0u, 0u);
            if (gr < N_NODES)
                va = *(const uint4*)(A + (size_t)gr * FDIM + k0 + cg * 8);
            *(uint4*)&As[r * SP + cg * 8] = va;
        }
        {
            int r  = tid >> 2;
            int cg = tid & 3;
            uint4 vb = *(const uint4*)(Wt + (size_t)r * FDIM + k0 + cg * 8);
            *(uint4*)&Bs[r * SP + cg * 8] = vb;
        }
        __syncthreads();

#pragma unroll
        for (int ks = 0; ks < 2; ks++) {
            const int kk = ks * 16 + tig * 2;
            unsigned af[4];
            int r0 = wid * 16 + gid;
            af[0] = *(const unsigned*)&As[(r0    ) * SP + kk];
            af[1] = *(const unsigned*)&As[(r0 + 8) * SP + kk];
            af[2] = *(const unsigned*)&As[(r0    ) * SP + kk + 8];
            af[3] = *(const unsigned*)&As[(r0 + 8) * SP + kk + 8];
#pragma unroll
            for (int nf = 0; nf < 8; nf++) {
                int c0 = nf * 8 + gid;
                unsigned bf[2];
                bf[0] = *(const unsigned*)&Bs[c0 * SP + kk];
                bf[1] = *(const unsigned*)&Bs[c0 * SP + kk + 8];
                mma_16816(acc[nf], af, bf);
            }
        }
        __syncthreads();
    }

#pragma unroll
    for (int nf = 0; nf < 8; nf++) {
        int c0 = nf * 8 + tig * 2;
        if (c0 >= NCLS) continue;
        float2 bv = *(const float2*)(bias + c0);
        int r0 = rowBase + wid * 16 + gid;
        int r1 = r0 + 8;
        if (r0 < N_NODES)
            *(float2*)(L + (size_t)r0 * NCLS + c0) =
                make_float2(acc[nf][0] + bv.x, acc[nf][1] + bv.y);
        if (r1 < N_NODES)
            *(float2*)(L + (size_t)r1 * NCLS + c0) =
                make_float2(acc[nf][2] + bv.x, acc[nf][3] + bv.y);
    }
}

// ---------------------------------------------------------------------------
// CSR gather aggregation (fp16 -> fp32 acc -> fp16), chunked by node range.
// ---------------------------------------------------------------------------
__device__ __forceinline__ void hacc8(float* acc, uint4 v)
{
    float2 f0 = __half22float2(*reinterpret_cast<__half2*>(&v.x));
    float2 f1 = __half22float2(*reinterpret_cast<__half2*>(&v.y));
    float2 f2 = __half22float2(*reinterpret_cast<__half2*>(&v.z));
    float2 f3 = __half22float2(*reinterpret_cast<__half2*>(&v.w));
    acc[0] += f0.x; acc[1] += f0.y;
    acc[2] += f1.x; acc[3] += f1.y;
    acc[4] += f2.x; acc[5] += f2.y;
    acc[6] += f3.x; acc[7] += f3.y;
}

__global__ __launch_bounds__(256) void aggregate_csr_h(
    const __half* __restrict__ Y, __half* __restrict__ H,
    const int* __restrict__ rowStart, const int* __restrict__ ssrc,
    int nodeOff, int nodeEnd)
{
    int node = nodeOff + blockIdx.x * 8 + (threadIdx.x >> 5);
    int lane = threadIdx.x & 31;
    if (node >= nodeEnd) return;

    const uint4* yb = (const uint4*)Y;
    float acc[8];
#pragma unroll
    for (int i = 0; i < 8; i++) acc[i] = 0.0f;

    hacc8(acc, __ldg(yb + (size_t)node * 32 + lane));   // self loop

    int e    = __ldg(rowStart + node);
    int eEnd = __ldg(rowStart + node + 1);

    for (; e + 4 <= eEnd; e += 4) {
        int s0 = __ldg(ssrc + e);
        int s1 = __ldg(ssrc + e + 1);
        int s2 = __ldg(ssrc + e + 2);
        int s3 = __ldg(ssrc + e + 3);
        uint4 v0 = __ldg(yb + (size_t)s0 * 32 + lane);
        uint4 v1 = __ldg(yb + (size_t)s1 * 32 + lane);
        uint4 v2 = __ldg(yb + (size_t)s2 * 32 + lane);
        uint4 v3 = __ldg(yb + (size_t)s3 * 32 + lane);
        hacc8(acc, v0); hacc8(acc, v1); hacc8(acc, v2); hacc8(acc, v3);
    }
    for (; e < eEnd; e++) {
        int s0 = __ldg(ssrc + e);
        hacc8(acc, __ldg(yb + (size_t)s0 * 32 + lane));
    }

    __half2 o0 = __floats2half2_rn(acc[0], acc[1]);
    __half2 o1 = __floats2half2_rn(acc[2], acc[3]);
    __half2 o2 = __floats2half2_rn(acc[4], acc[5]);
    __half2 o3 = __floats2half2_rn(acc[6], acc[7]);
    uint4 st;
    st.x = *(unsigned*)&o0; st.y = *(unsigned*)&o1;
    st.z = *(unsigned*)&o2; st.w = *(unsigned*)&o3;
    *(uint4*)(H + (size_t)node * FDIM + lane * 8) = st;
}

// ---------------------------------------------------------------------------
// Fused head: out[r] = log_softmax( sum_{nz in PvT row r} val * logits[col] ).
// One warp per output row; no atomics, no zero-init, no intermediate buffer.
// Rows with no nonzeros correctly give log_softmax(0-vector) = -log(40).
// ---------------------------------------------------------------------------
__global__ __launch_bounds__(256) void head_kernel(
    const float* __restrict__ L, const int* __restrict__ prs,
    const int* __restrict__ pcolS, const float* __restrict__ pvalS,
    float* __restrict__ out)
{
    int row  = blockIdx.x * 8 + (threadIdx.x >> 5);
    int lane = threadIdx.x & 31;
    if (row >= N_NODES) return;

    float x0 = 0.0f, x1 = 0.0f;
    int e    = __ldg(prs + row);
    int eEnd = __ldg(prs + row + 1);
    for (; e < eEnd; e++) {
        int   c = __ldg(pcolS + e);
        float v = __ldg(pvalS + e);
        const float* lr = L + (size_t)c * NCLS;
        x0 = fmaf(v, __ldg(lr + lane), x0);
        if (lane < 8) x1 = fmaf(v, __ldg(lr + 32 + lane), x1);
    }

    float m = fmaxf(x0, (lane < 8) ? x1 : -INFINITY);
#pragma unroll
    for (int off = 16; off > 0; off >>= 1)
        m = fmaxf(m, __shfl_xor_sync(0xffffffffu, m, off));
    float s = __expf(x0 - m) + ((lane < 8) ? __expf(x1 - m) : 0.0f);
#pragma unroll
    for (int off = 16; off > 0; off >>= 1)
        s += __shfl_xor_sync(0xffffffffu, s, off);
    float ls = logf(s);
    float* o = out + (size_t)row * NCLS;
    o[lane] = x0 - m - ls;
    if (lane < 8) o[32 + lane] = x1 - m - ls;
}

// ---------------------------------------------------------------------------
extern "C" void kernel_launch(void* const* d_in, const int* in_sizes, int n_in,
                              void* d_out, int out_size)
{
    const float* x    = (const float*)d_in[0];
    const int*   esrc = (const int*)  d_in[1];
    const int*   edst = (const int*)  d_in[2];
    const int*   prow = (const int*)  d_in[3];
    const int*   pcol = (const int*)  d_in[4];
    const float* pval = (const float*)d_in[5];
    const float* w1   = (const float*)d_in[6];
    const float* b1   = (const float*)d_in[7];
    const float* w2   = (const float*)d_in[8];
    const float* b2   = (const float*)d_in[9];
    const float* wfc  = (const float*)d_in[10];
    const float* bfc  = (const float*)d_in[11];
    const int E   = in_sizes[1];
    const int nnz = in_sizes[3];

    __half *Y1h, *Y2h, *h1h, *h2h, *w1t, *w2t, *wfct;
    float *bfcp, *logits, *pvalS;
    int *ssrc, *rowStart, *deg, *cursor;
    int *pdeg, *pcursor, *prowStart, *pcolS;
    cudaGetSymbolAddress((void**)&Y1h,       g_Y1h);
    cudaGetSymbolAddress((void**)&Y2h,       g_Y2h);
    cudaGetSymbolAddress((void**)&h1h,       g_h1h);
    cudaGetSymbolAddress((void**)&h2h,       g_h2h);
    cudaGetSymbolAddress((void**)&w1t,       g_w1t);
    cudaGetSymbolAddress((void**)&w2t,       g_w2t);
    cudaGetSymbolAddress((void**)&wfct,      g_wfct);
    cudaGetSymbolAddress((void**)&bfcp,      g_bfcp);
    cudaGetSymbolAddress((void**)&logits,    g_logits);
    cudaGetSymbolAddress((void**)&ssrc,      g_sortedSrc);
    cudaGetSymbolAddress((void**)&rowStart,  g_rowStart);
    cudaGetSymbolAddress((void**)&deg,       g_deg);
    cudaGetSymbolAddress((void**)&cursor,    g_cursor);
    cudaGetSymbolAddress((void**)&pdeg,      g_pdeg);
    cudaGetSymbolAddress((void**)&pcursor,   g_pcursor);
    cudaGetSymbolAddress((void**)&prowStart, g_prowStart);
    cudaGetSymbolAddress((void**)&pcolS,     g_pcolS);
    cudaGetSymbolAddress((void**)&pvalS,     g_pvalS);

    static cudaStream_t side = nullptr;
    static cudaEvent_t evFork = nullptr, evCSR = nullptr, evJoin = nullptr;
    static cudaEvent_t evFC = nullptr;
    static cudaEvent_t evA[NCHUNK] = {};
    static cudaEvent_t evB[NCHUNK] = {};
    if (!side) {
        cudaStreamCreateWithFlags(&side, cudaStreamNonBlocking);
        cudaEventCreateWithFlags(&evFork, cudaEventDisableTiming);
        cudaEventCreateWithFlags(&evCSR,  cudaEventDisableTiming);
        cudaEventCreateWithFlags(&evJoin, cudaEventDisableTiming);
        cudaEventCreateWithFlags(&evFC,   cudaEventDisableTiming);
        for (int c = 0; c < NCHUNK; c++) {
            cudaEventCreateWithFlags(&evA[c], cudaEventDisableTiming);
            cudaEventCreateWithFlags(&evB[c], cudaEventDisableTiming);
        }
    }

    // --- fork: CSR builds + converts on side stream (hidden under G1) ---
    cudaEventRecord(evFork, 0);
    cudaStreamWaitEvent(side, evFork, 0);
    zero2_i32<<<(N_NODES + 255) / 256, 256, 0, side>>>(deg, cursor, N_NODES);
    hist_kernel<<<(E / 4 + 255) / 256, 256, 0, side>>>(edst, deg, E);
    scan_kernel<<<1, 1024, 0, side>>>(deg, rowStart);
    scatter_kernel<<<(E / 4 + 255) / 256, 256, 0, side>>>(esrc, edst, rowStart,
                                                          cursor, ssrc, E);
    cudaEventRecord(evCSR, side);
    // PvT CSR (small; hidden)
    zero2_i32<<<(N_NODES + 255) / 256, 256, 0, side>>>(pdeg, pcursor, N_NODES);
    hist_kernel<<<(nnz / 4 + 255) / 256, 256, 0, side>>>(prow, pdeg, nnz);
    scan_kernel<<<1, 1024, 0, side>>>(pdeg, prowStart);
    pvt_scatter_kernel<<<(nnz + 255) / 256, 256, 0, side>>>(
        prow, pcol, pval, prowStart, pcursor, pcolS, pvalS, nnz);
    wconv_kernel<<<FDIM, FDIM, 0, side>>>(w2, w2t);
    wfc_conv_kernel<<<NPAD, FDIM, 0, side>>>(wfc, wfct);
    bfc_pad_kernel<<<1, NPAD, 0, side>>>(bfc, bfcp);

    // --- main: W1 convert + conv1 GEMM (reads fp32 x directly) ---
    wconv_kernel<<<FDIM, FDIM>>>(w1, w1t);
    dim3 g1_grid(FDIM / 128, (N_NODES + 127) / 128);
    gemm_mma<true><<<g1_grid, 256>>>(x, w1t, b1, Y1h, 0);

    // --- A1 (main, chunked) pipelined with G2 (side, chunked) ---
    cudaStreamWaitEvent(0, evCSR, 0);
    for (int c = 0; c < NCHUNK; c++) {
        int n0 = c * CHUNK_ROWS;
        int n1 = min(N_NODES, n0 + CHUNK_ROWS);
        int nb = (n1 - n0 + 7) / 8;
        aggregate_csr_h<<<nb, 256>>>(Y1h, h1h, rowStart, ssrc, n0, n1);
        cudaEventRecord(evA[c], 0);
        cudaStreamWaitEvent(side, evA[c], 0);
        dim3 g2_grid(FDIM / 128, (n1 - n0 + 127) / 128);
        gemm_mma<false><<<g2_grid, 256, 0, side>>>(h1h, w2t, b2, Y2h, n0);
    }
    cudaEventRecord(evJoin, side);
    cudaStreamWaitEvent(0, evJoin, 0);

    // --- A2 (main, chunked) pipelined with FC (side, chunked) ---
    for (int c = 0; c < NCHUNK; c++) {
        int n0 = c * CHUNK_ROWS;
        int n1 = min(N_NODES, n0 + CHUNK_ROWS);
        int nb = (n1 - n0 + 7) / 8;
        aggregate_csr_h<<<nb, 256>>>(Y2h, h2h, rowStart, ssrc, n0, n1);
        cudaEventRecord(evB[c], 0);
        cudaStreamWaitEvent(side, evB[c], 0);
        fc_mma<<<dim3(1, (n1 - n0 + 127) / 128), 256, 0, side>>>(
            h2h, wfct, bfcp, logits, n0);
    }
    cudaEventRecord(evFC, side);
    cudaStreamWaitEvent(0, evFC, 0);

    // --- fused PvT @ logits + log-softmax ---
    head_kernel<<<(N_NODES + 7) / 8, 256>>>(logits, prowStart, pcolS, pvalS,
                                            (float*)d_out);
}

// round 11
// speedup vs baseline: 1.6319x; 1.6319x over previous
#include <cuda_runtime.h>
#include <cuda_fp16.h>
#include <math.h>

#define N_NODES 50000
#define FDIM    256
#define NCLS    40
#define NPAD    64
#define MAX_E   1700000
#define SP      40          // smem row stride in halves (conflict-free frags)
#define CHUNK_ROWS 12544    // 98 * 128
#define NCHUNK  4

// Scratch (device globals only — no runtime allocation)
__device__ __half g_Y1h[(size_t)N_NODES * FDIM];   // conv1 GEMM out
__device__ __half g_Y2h[(size_t)N_NODES * FDIM];   // conv2 GEMM out
__device__ __half g_h1h[(size_t)N_NODES * FDIM];   // conv1 aggregate
__device__ __half g_h2h[(size_t)N_NODES * FDIM];   // conv2 aggregate
__device__ __half g_w1t[FDIM * FDIM];              // W1^T fp16 [n][k]
__device__ __half g_w2t[FDIM * FDIM];              // W2^T fp16 [n][k]
__device__ __half g_wfct[NPAD * FDIM];             // Wfc^T fp16 [n][k], padded
__device__ float  g_bfcp[NPAD];
__device__ float  g_logits[(size_t)N_NODES * NCLS];
__device__ int    g_sortedSrc[MAX_E];
__device__ int    g_rowStart[N_NODES + 1];
__device__ int    g_deg[N_NODES];
__device__ int    g_cursor[N_NODES];
// PvT CSR (row-sorted)
__device__ int    g_pdeg[N_NODES];
__device__ int    g_pcursor[N_NODES];
__device__ int    g_prowStart[N_NODES + 1];
__device__ int    g_pcolS[N_NODES + 64];
__device__ float  g_pvalS[N_NODES + 64];

// ---------------------------------------------------------------------------
// Weight converts
// ---------------------------------------------------------------------------
__global__ __launch_bounds__(256) void wconv_kernel(
    const float* __restrict__ W, __half* __restrict__ Wt)
{
    int n = blockIdx.x;
    int k = threadIdx.x;
    Wt[n * FDIM + k] = __float2half(__ldg(W + k * FDIM + n));
}

__global__ __launch_bounds__(256) void wfc_conv_kernel(
    const float* __restrict__ Wfc, __half* __restrict__ Wt)
{
    int n = blockIdx.x;           // 0..63
    int k = threadIdx.x;
    Wt[n * FDIM + k] = (n < NCLS) ? __float2half(__ldg(Wfc + k * NCLS + n))
                                  : __float2half(0.0f);
}

__global__ __launch_bounds__(64) void bfc_pad_kernel(
    const float* __restrict__ bfc, float* __restrict__ bp)
{
    int i = threadIdx.x;
    bp[i] = (i < NCLS) ? __ldg(bfc + i) : 0.0f;
}

// ---------------------------------------------------------------------------
// CSR build (round-9 proven versions: 1 element/thread)
// ---------------------------------------------------------------------------
__global__ __launch_bounds__(256) void zero2_i32(int* __restrict__ a,
                                                 int* __restrict__ b, int n)
{
    int i = blockIdx.x * blockDim.x + threadIdx.x;
    if (i < n) { a[i] = 0; b[i] = 0; }
}

__global__ __launch_bounds__(256) void hist_kernel(
    const int* __restrict__ dst, int* __restrict__ deg, int E)
{
    int i = blockIdx.x * blockDim.x + threadIdx.x;
    if (i < E) atomicAdd(&deg[__ldg(dst + i)], 1);
}

__global__ __launch_bounds__(1024) void scan_kernel(
    const int* __restrict__ deg, int* __restrict__ rowStart)
{
    __shared__ int sums[1024];
    const int tid = threadIdx.x;
    const int CH  = (N_NODES + 1023) / 1024;
    const int base = tid * CH;
    int s = 0;
    for (int i = 0; i < CH; i++) {
        int idx = base + i;
        if (idx < N_NODES) s += deg[idx];
    }
    sums[tid] = s;
    __syncthreads();
    for (int off = 1; off < 1024; off <<= 1) {
        int v = (tid >= off) ? sums[tid - off] : 0;
        __syncthreads();
        sums[tid] += v;
        __syncthreads();
    }
    int run = sums[tid] - s;
    for (int i = 0; i < CH; i++) {
        int idx = base + i;
        if (idx < N_NODES) { rowStart[idx] = run; run += deg[idx]; }
    }
    if (tid == 1023) rowStart[N_NODES] = run;
}

__global__ __launch_bounds__(256) void scatter_kernel(
    const int* __restrict__ src, const int* __restrict__ dst,
    const int* __restrict__ rowStart, int* __restrict__ cursor,
    int* __restrict__ sortedSrc, int E)
{
    int i = blockIdx.x * blockDim.x + threadIdx.x;
    if (i >= E) return;
    int d = __ldg(dst + i);
    int pos = __ldg(rowStart + d) + atomicAdd(&cursor[d], 1);
    sortedSrc[pos] = __ldg(src + i);
}

// PvT scatter: carries (col, val) into row-sorted order
__global__ __launch_bounds__(256) void pvt_scatter_kernel(
    const int* __restrict__ prow, const int* __restrict__ pcol,
    const float* __restrict__ pval, const int* __restrict__ rowStart,
    int* __restrict__ cursor, int* __restrict__ colS,
    float* __restrict__ valS, int nnz)
{
    int i = blockIdx.x * blockDim.x + threadIdx.x;
    if (i >= nnz) return;
    int r = __ldg(prow + i);
    int pos = __ldg(rowStart + r) + atomicAdd(&cursor[r], 1);
    colS[pos] = __ldg(pcol + i);
    valS[pos] = __ldg(pval + i);
}

// ---------------------------------------------------------------------------
// Tensor-core GEMM: Y = half(relu(A[M,256] @ W[256,256] + bias)).
// ---------------------------------------------------------------------------
__device__ __forceinline__ void mma_16816(float c[4], const unsigned a[4],
                                          const unsigned b[2])
{
    asm volatile(
        "mma.sync.aligned.m16n8k16.row.col.f32.f16.f16.f32 "
        "{%0,%1,%2,%3}, {%4,%5,%6,%7}, {%8,%9}, {%0,%1,%2,%3};\n"
        : "+f"(c[0]), "+f"(c[1]), "+f"(c[2]), "+f"(c[3])
        : "r"(a[0]), "r"(a[1]), "r"(a[2]), "r"(a[3]), "r"(b[0]), "r"(b[1]));
}

template <bool A_FP32>
__global__ __launch_bounds__(256, 2) void gemm_mma(
    const void* __restrict__ Av, const __half* __restrict__ Wt,
    const float* __restrict__ bias, __half* __restrict__ Y, int rowOff)
{
    __shared__ __half As[128 * SP];
    __shared__ __half Bs[128 * SP];

    const int tid   = threadIdx.x;
    const int wid   = tid >> 5;
    const int lane  = tid & 31;
    const int gid   = lane >> 2;
    const int tig   = lane & 3;
    const int warp_m = wid & 3;
    const int warp_n = wid >> 2;
    const int rowBase = rowOff + blockIdx.y * 128;
    const int colBase = blockIdx.x * 128;

    float acc[2][8][4];
#pragma unroll
    for (int mf = 0; mf < 2; mf++)
#pragma unroll
        for (int nf = 0; nf < 8; nf++)
#pragma unroll
            for (int j = 0; j < 4; j++) acc[mf][nf][j] = 0.0f;

    for (int k0 = 0; k0 < FDIM; k0 += 32) {
#pragma unroll
        for (int i = 0; i < 2; i++) {
            int idx = tid + i * 256;
            int r   = idx >> 2;
            int cg  = idx & 3;
            int gr  = rowBase + r;
            uint4 va;
            if (A_FP32) {
                float4 f0 = make_float4(0.f, 0.f, 0.f, 0.f);
                float4 f1 = make_float4(0.f, 0.f, 0.f, 0.f);
                if (gr < N_NODES) {
                    const float* ap = (const float*)Av + (size_t)gr * FDIM + k0 + cg * 8;
                    f0 = *(const float4*)ap;
                    f1 = *(const float4*)(ap + 4);
                }
                __half2 h0 = __floats2half2_rn(f0.x, f0.y);
                __half2 h1 = __floats2half2_rn(f0.z, f0.w);
                __half2 h2 = __floats2half2_rn(f1.x, f1.y);
                __half2 h3 = __floats2half2_rn(f1.z, f1.w);
                va = make_uint4(*(unsigned*)&h0, *(unsigned*)&h1,
                                *(unsigned*)&h2, *(unsigned*)&h3);
            } else {
                va = make_uint4(0u, 0u, 0u, 0u);
                if (gr < N_NODES)
                    va = *(const uint4*)((const __half*)Av + (size_t)gr * FDIM + k0 + cg * 8);
            }
            *(uint4*)&As[r * SP + cg * 8] = va;
            uint4 vb = *(const uint4*)(Wt + (size_t)(colBase + r) * FDIM + k0 + cg * 8);
            *(uint4*)&Bs[r * SP + cg * 8] = vb;
        }
        __syncthreads();

#pragma unroll
        for (int ks = 0; ks < 2; ks++) {
            const int kk = ks * 16 + tig * 2;
            unsigned af[2][4];
#pragma unroll
            for (int mf = 0; mf < 2; mf++) {
                int r0 = warp_m * 32 + mf * 16 + gid;
                af[mf][0] = *(const unsigned*)&As[(r0    ) * SP + kk];
                af[mf][1] = *(const unsigned*)&As[(r0 + 8) * SP + kk];
                af[mf][2] = *(const unsigned*)&As[(r0    ) * SP + kk + 8];
                af[mf][3] = *(const unsigned*)&As[(r0 + 8) * SP + kk + 8];
            }
#pragma unroll
            for (int nf = 0; nf < 8; nf++) {
                int c0 = warp_n * 64 + nf * 8 + gid;
                unsigned bf[2];
                bf[0] = *(const unsigned*)&Bs[c0 * SP + kk];
                bf[1] = *(const unsigned*)&Bs[c0 * SP + kk + 8];
                mma_16816(acc[0][nf], af[0], bf);
                mma_16816(acc[1][nf], af[1], bf);
            }
        }
        __syncthreads();
    }

    float2 bv[8];
#pragma unroll
    for (int nf = 0; nf < 8; nf++)
        bv[nf] = *(const float2*)(bias + colBase + warp_n * 64 + nf * 8 + tig * 2);

#pragma unroll
    for (int mf = 0; mf < 2; mf++) {
        int gr0 = rowBase + warp_m * 32 + mf * 16 + gid;
        int gr1 = gr0 + 8;
#pragma unroll
        for (int nf = 0; nf < 8; nf++) {
            int col = colBase + warp_n * 64 + nf * 8 + tig * 2;
            if (gr0 < N_NODES) {
                __half2 h = __floats2half2_rn(
                    fmaxf(acc[mf][nf][0] + bv[nf].x, 0.f),
                    fmaxf(acc[mf][nf][1] + bv[nf].y, 0.f));
                *(__half2*)(Y + (size_t)gr0 * FDIM + col) = h;
            }
            if (gr1 < N_NODES) {
                __half2 h = __floats2half2_rn(
                    fmaxf(acc[mf][nf][2] + bv[nf].x, 0.f),
                    fmaxf(acc[mf][nf][3] + bv[nf].y, 0.f));
                *(__half2*)(Y + (size_t)gr1 * FDIM + col) = h;
            }
        }
    }
}

// ---------------------------------------------------------------------------
// FC via tensor cores: logits[N,40] = h2[N,256](fp16) @ WfcT + bfc (fp32 out).
// ---------------------------------------------------------------------------
__global__ __launch_bounds__(256, 2) void fc_mma(
    const __half* __restrict__ A, const __half* __restrict__ Wt,
    const float* __restrict__ bias, float* __restrict__ L)
{
    __shared__ __half As[128 * SP];
    __shared__ __half Bs[64 * SP];

    const int tid  = threadIdx.x;
    const int wid  = tid >> 5;
    const int lane = tid & 31;
    const int gid  = lane >> 2;
    const int tig  = lane & 3;
    const int rowBase = blockIdx.y * 128;

    float acc[8][4];
#pragma unroll
    for (int nf = 0; nf < 8; nf++)
#pragma unroll
        for (int j = 0; j < 4; j++) acc[nf][j] = 0.0f;

    for (int k0 = 0; k0 < FDIM; k0 += 32) {
#pragma unroll
        for (int i = 0; i < 2; i++) {
            int idx = tid + i * 256;
            int r   = idx >> 2;
            int cg  = idx & 3;
            int gr  = rowBase + r;
            uint4 va = make_uint4(0u, 0u, 0u, 0u);
            if (gr < N_NODES)
                va = *(const uint4*)(A + (size_t)gr * FDIM + k0 + cg * 8);
            *(uint4*)&As[r * SP + cg * 8] = va;
        }
        {
            int r  = tid >> 2;
            int cg = tid & 3;
            uint4 vb = *(const uint4*)(Wt + (size_t)r * FDIM + k0 + cg * 8);
            *(uint4*)&Bs[r * SP + cg * 8] = vb;
        }
        __syncthreads();

#pragma unroll
        for (int ks = 0; ks < 2; ks++) {
            const int kk = ks * 16 + tig * 2;
            unsigned af[4];
            int r0 = wid * 16 + gid;
            af[0] = *(const unsigned*)&As[(r0    ) * SP + kk];
            af[1] = *(const unsigned*)&As[(r0 + 8) * SP + kk];
            af[2] = *(const unsigned*)&As[(r0    ) * SP + kk + 8];
            af[3] = *(const unsigned*)&As[(r0 + 8) * SP + kk + 8];
#pragma unroll
            for (int nf = 0; nf < 8; nf++) {
                int c0 = nf * 8 + gid;
                unsigned bf[2];
                bf[0] = *(const unsigned*)&Bs[c0 * SP + kk];
                bf[1] = *(const unsigned*)&Bs[c0 * SP + kk + 8];
                mma_16816(acc[nf], af, bf);
            }
        }
        __syncthreads();
    }

#pragma unroll
    for (int nf = 0; nf < 8; nf++) {
        int c0 = nf * 8 + tig * 2;
        if (c0 >= NCLS) continue;
        float2 bv = *(const float2*)(bias + c0);
        int r0 = rowBase + wid * 16 + gid;
        int r1 = r0 + 8;
        if (r0 < N_NODES)
            *(float2*)(L + (size_t)r0 * NCLS + c0) =
                make_float2(acc[nf][0] + bv.x, acc[nf][1] + bv.y);
        if (r1 < N_NODES)
            *(float2*)(L + (size_t)r1 * NCLS + c0) =
                make_float2(acc[nf][2] + bv.x, acc[nf][3] + bv.y);
    }
}

// ---------------------------------------------------------------------------
// CSR gather aggregation (fp16 -> fp32 acc -> fp16), chunked by node range.
// ---------------------------------------------------------------------------
__device__ __forceinline__ void hacc8(float* acc, uint4 v)
{
    float2 f0 = __half22float2(*reinterpret_cast<__half2*>(&v.x));
    float2 f1 = __half22float2(*reinterpret_cast<__half2*>(&v.y));
    float2 f2 = __half22float2(*reinterpret_cast<__half2*>(&v.z));
    float2 f3 = __half22float2(*reinterpret_cast<__half2*>(&v.w));
    acc[0] += f0.x; acc[1] += f0.y;
    acc[2] += f1.x; acc[3] += f1.y;
    acc[4] += f2.x; acc[5] += f2.y;
    acc[6] += f3.x; acc[7] += f3.y;
}

__global__ __launch_bounds__(256) void aggregate_csr_h(
    const __half* __restrict__ Y, __half* __restrict__ H,
    const int* __restrict__ rowStart, const int* __restrict__ ssrc,
    int nodeOff, int nodeEnd)
{
    int node = nodeOff + blockIdx.x * 8 + (threadIdx.x >> 5);
    int lane = threadIdx.x & 31;
    if (node >= nodeEnd) return;

    const uint4* yb = (const uint4*)Y;
    float acc[8];
#pragma unroll
    for (int i = 0; i < 8; i++) acc[i] = 0.0f;

    hacc8(acc, __ldg(yb + (size_t)node * 32 + lane));   // self loop

    int e    = __ldg(rowStart + node);
    int eEnd = __ldg(rowStart + node + 1);

    for (; e + 4 <= eEnd; e += 4) {
        int s0 = __ldg(ssrc + e);
        int s1 = __ldg(ssrc + e + 1);
        int s2 = __ldg(ssrc + e + 2);
        int s3 = __ldg(ssrc + e + 3);
        uint4 v0 = __ldg(yb + (size_t)s0 * 32 + lane);
        uint4 v1 = __ldg(yb + (size_t)s1 * 32 + lane);
        uint4 v2 = __ldg(yb + (size_t)s2 * 32 + lane);
        uint4 v3 = __ldg(yb + (size_t)s3 * 32 + lane);
        hacc8(acc, v0); hacc8(acc, v1); hacc8(acc, v2); hacc8(acc, v3);
    }
    for (; e < eEnd; e++) {
        int s0 = __ldg(ssrc + e);
        hacc8(acc, __ldg(yb + (size_t)s0 * 32 + lane));
    }

    __half2 o0 = __floats2half2_rn(acc[0], acc[1]);
    __half2 o1 = __floats2half2_rn(acc[2], acc[3]);
    __half2 o2 = __floats2half2_rn(acc[4], acc[5]);
    __half2 o3 = __floats2half2_rn(acc[6], acc[7]);
    uint4 st;
    st.x = *(unsigned*)&o0; st.y = *(unsigned*)&o1;
    st.z = *(unsigned*)&o2; st.w = *(unsigned*)&o3;
    *(uint4*)(H + (size_t)node * FDIM + lane * 8) = st;
}

// ---------------------------------------------------------------------------
// Fused head: out[r] = log_softmax( sum_{nz in PvT row r} val * logits[col] ).
// One warp per output row; no atomics, no zero-init, no intermediate buffer.
// Rows with no nonzeros correctly give log_softmax(0-vector) = -log(40).
// ---------------------------------------------------------------------------
__global__ __launch_bounds__(256) void head_kernel(
    const float* __restrict__ L, const int* __restrict__ prs,
    const int* __restrict__ pcolS, const float* __restrict__ pvalS,
    float* __restrict__ out)
{
    int row  = blockIdx.x * 8 + (threadIdx.x >> 5);
    int lane = threadIdx.x & 31;
    if (row >= N_NODES) return;

    float x0 = 0.0f, x1 = 0.0f;
    int e    = __ldg(prs + row);
    int eEnd = __ldg(prs + row + 1);
    for (; e < eEnd; e++) {
        int   c = __ldg(pcolS + e);
        float v = __ldg(pvalS + e);
        const float* lr = L + (size_t)c * NCLS;
        x0 = fmaf(v, __ldg(lr + lane), x0);
        if (lane < 8) x1 = fmaf(v, __ldg(lr + 32 + lane), x1);
    }

    float m = fmaxf(x0, (lane < 8) ? x1 : -INFINITY);
#pragma unroll
    for (int off = 16; off > 0; off >>= 1)
        m = fmaxf(m, __shfl_xor_sync(0xffffffffu, m, off));
    float s = __expf(x0 - m) + ((lane < 8) ? __expf(x1 - m) : 0.0f);
#pragma unroll
    for (int off = 16; off > 0; off >>= 1)
        s += __shfl_xor_sync(0xffffffffu, s, off);
    float ls = logf(s);
    float* o = out + (size_t)row * NCLS;
    o[lane] = x0 - m - ls;
    if (lane < 8) o[32 + lane] = x1 - m - ls;
}

// ---------------------------------------------------------------------------
extern "C" void kernel_launch(void* const* d_in, const int* in_sizes, int n_in,
                              void* d_out, int out_size)
{
    const float* x    = (const float*)d_in[0];
    const int*   esrc = (const int*)  d_in[1];
    const int*   edst = (const int*)  d_in[2];
    const int*   prow = (const int*)  d_in[3];
    const int*   pcol = (const int*)  d_in[4];
    const float* pval = (const float*)d_in[5];
    const float* w1   = (const float*)d_in[6];
    const float* b1   = (const float*)d_in[7];
    const float* w2   = (const float*)d_in[8];
    const float* b2   = (const float*)d_in[9];
    const float* wfc  = (const float*)d_in[10];
    const float* bfc  = (const float*)d_in[11];
    const int E   = in_sizes[1];
    const int nnz = in_sizes[3];

    __half *Y1h, *Y2h, *h1h, *h2h, *w1t, *w2t, *wfct;
    float *bfcp, *logits, *pvalS;
    int *ssrc, *rowStart, *deg, *cursor;
    int *pdeg, *pcursor, *prowStart, *pcolS;
    cudaGetSymbolAddress((void**)&Y1h,       g_Y1h);
    cudaGetSymbolAddress((void**)&Y2h,       g_Y2h);
    cudaGetSymbolAddress((void**)&h1h,       g_h1h);
    cudaGetSymbolAddress((void**)&h2h,       g_h2h);
    cudaGetSymbolAddress((void**)&w1t,       g_w1t);
    cudaGetSymbolAddress((void**)&w2t,       g_w2t);
    cudaGetSymbolAddress((void**)&wfct,      g_wfct);
    cudaGetSymbolAddress((void**)&bfcp,      g_bfcp);
    cudaGetSymbolAddress((void**)&logits,    g_logits);
    cudaGetSymbolAddress((void**)&ssrc,      g_sortedSrc);
    cudaGetSymbolAddress((void**)&rowStart,  g_rowStart);
    cudaGetSymbolAddress((void**)&deg,       g_deg);
    cudaGetSymbolAddress((void**)&cursor,    g_cursor);
    cudaGetSymbolAddress((void**)&pdeg,      g_pdeg);
    cudaGetSymbolAddress((void**)&pcursor,   g_pcursor);
    cudaGetSymbolAddress((void**)&prowStart, g_prowStart);
    cudaGetSymbolAddress((void**)&pcolS,     g_pcolS);
    cudaGetSymbolAddress((void**)&pvalS,     g_pvalS);

    static cudaStream_t side = nullptr;
    static cudaEvent_t evFork = nullptr, evCSR = nullptr, evJoin = nullptr;
    static cudaEvent_t evA[NCHUNK] = {};
    if (!side) {
        cudaStreamCreateWithFlags(&side, cudaStreamNonBlocking);
        cudaEventCreateWithFlags(&evFork, cudaEventDisableTiming);
        cudaEventCreateWithFlags(&evCSR,  cudaEventDisableTiming);
        cudaEventCreateWithFlags(&evJoin, cudaEventDisableTiming);
        for (int c = 0; c < NCHUNK; c++)
            cudaEventCreateWithFlags(&evA[c], cudaEventDisableTiming);
    }

    // --- fork: CSR build + converts + PvT CSR on side stream ---
    cudaEventRecord(evFork, 0);
    cudaStreamWaitEvent(side, evFork, 0);
    zero2_i32<<<(N_NODES + 255) / 256, 256, 0, side>>>(deg, cursor, N_NODES);
    hist_kernel<<<(E + 255) / 256, 256, 0, side>>>(edst, deg, E);
    scan_kernel<<<1, 1024, 0, side>>>(deg, rowStart);
    scatter_kernel<<<(E + 255) / 256, 256, 0, side>>>(esrc, edst, rowStart,
                                                      cursor, ssrc, E);
    cudaEventRecord(evCSR, side);
    wconv_kernel<<<FDIM, FDIM, 0, side>>>(w2, w2t);
    wfc_conv_kernel<<<NPAD, FDIM, 0, side>>>(wfc, wfct);
    bfc_pad_kernel<<<1, NPAD, 0, side>>>(bfc, bfcp);
    // PvT CSR build (fills side-stream idle gap before G2 chunk 0)
    zero2_i32<<<(N_NODES + 255) / 256, 256, 0, side>>>(pdeg, pcursor, N_NODES);
    hist_kernel<<<(nnz + 255) / 256, 256, 0, side>>>(prow, pdeg, nnz);
    scan_kernel<<<1, 1024, 0, side>>>(pdeg, prowStart);
    pvt_scatter_kernel<<<(nnz + 255) / 256, 256, 0, side>>>(
        prow, pcol, pval, prowStart, pcursor, pcolS, pvalS, nnz);

    // --- main: W1 convert + conv1 GEMM (reads fp32 x directly) ---
    wconv_kernel<<<FDIM, FDIM>>>(w1, w1t);
    dim3 g1_grid(FDIM / 128, (N_NODES + 127) / 128);
    gemm_mma<true><<<g1_grid, 256>>>(x, w1t, b1, Y1h, 0);

    // --- A1 (main, chunked) pipelined with G2 (side, chunked) ---
    cudaStreamWaitEvent(0, evCSR, 0);
    for (int c = 0; c < NCHUNK; c++) {
        int n0 = c * CHUNK_ROWS;
        int n1 = min(N_NODES, n0 + CHUNK_ROWS);
        int nb = (n1 - n0 + 7) / 8;
        aggregate_csr_h<<<nb, 256>>>(Y1h, h1h, rowStart, ssrc, n0, n1);
        cudaEventRecord(evA[c], 0);
        cudaStreamWaitEvent(side, evA[c], 0);
        dim3 g2_grid(FDIM / 128, (n1 - n0 + 127) / 128);
        gemm_mma<false><<<g2_grid, 256, 0, side>>>(h1h, w2t, b2, Y2h, n0);
    }
    cudaEventRecord(evJoin, side);
    cudaStreamWaitEvent(0, evJoin, 0);

    // --- A2 + head (main, round-9 structure) ---
    aggregate_csr_h<<<(N_NODES + 7) / 8, 256>>>(Y2h, h2h, rowStart, ssrc,
                                                0, N_NODES);
    fc_mma<<<dim3(1, (N_NODES + 127) / 128), 256>>>(h2h, wfct, bfcp, logits);
    head_kernel<<<(N_NODES + 7) / 8, 256>>>(logits, prowStart, pcolS, pvalS,
                                            (float*)d_out);
}

// round 13
// speedup vs baseline: 1.8300x; 1.1214x over previous
#include <cuda_runtime.h>
#include <cuda_fp16.h>
#include <math.h>

#define N_NODES 50000
#define FDIM    256
#define NCLS    40
#define NPAD    64
#define MAX_E   1700000
#define SP      40          // smem row stride in halves (conflict-free frags)
#define CHUNK_ROWS 12544    // 98 * 128
#define NCHUNK  4

// Scratch (device globals only — no runtime allocation)
__device__ __half g_Y1h[(size_t)N_NODES * FDIM];   // conv1 GEMM out
__device__ __half g_Y2h[(size_t)N_NODES * FDIM];   // conv2 GEMM out
__device__ __half g_h1h[(size_t)N_NODES * FDIM];   // conv1 aggregate
__device__ __half g_h2h[(size_t)N_NODES * FDIM];   // conv2 aggregate
__device__ __half g_w1t[FDIM * FDIM];              // W1^T fp16 [n][k]
__device__ __half g_w2t[FDIM * FDIM];              // W2^T fp16 [n][k]
__device__ __half g_wfct[NPAD * FDIM];             // Wfc^T fp16 [n][k], padded
__device__ float  g_bfcp[NPAD];
__device__ float  g_logits[(size_t)N_NODES * NCLS];
__device__ int    g_sortedSrc[MAX_E];
__device__ int    g_rowStart[N_NODES + 1];
__device__ int    g_deg[N_NODES];
__device__ int    g_cursor[N_NODES];
// PvT CSR (row-sorted)
__device__ int    g_pdeg[N_NODES];
__device__ int    g_pcursor[N_NODES];
__device__ int    g_prowStart[N_NODES + 1];
__device__ int    g_pcolS[N_NODES + 64];
__device__ float  g_pvalS[N_NODES + 64];

// ---------------------------------------------------------------------------
// Weight converts
// ---------------------------------------------------------------------------
__global__ __launch_bounds__(256) void wconv_kernel(
    const float* __restrict__ W, __half* __restrict__ Wt)
{
    int n = blockIdx.x;
    int k = threadIdx.x;
    Wt[n * FDIM + k] = __float2half(__ldg(W + k * FDIM + n));
}

__global__ __launch_bounds__(256) void wfc_conv_kernel(
    const float* __restrict__ Wfc, __half* __restrict__ Wt)
{
    int n = blockIdx.x;           // 0..63
    int k = threadIdx.x;
    Wt[n * FDIM + k] = (n < NCLS) ? __float2half(__ldg(Wfc + k * NCLS + n))
                                  : __float2half(0.0f);
}

__global__ __launch_bounds__(64) void bfc_pad_kernel(
    const float* __restrict__ bfc, float* __restrict__ bp)
{
    int i = threadIdx.x;
    bp[i] = (i < NCLS) ? __ldg(bfc + i) : 0.0f;
}

// ---------------------------------------------------------------------------
// CSR build (round-9 proven versions: 1 element/thread)
// ---------------------------------------------------------------------------
__global__ __launch_bounds__(256) void zero2_i32(int* __restrict__ a,
                                                 int* __restrict__ b, int n)
{
    int i = blockIdx.x * blockDim.x + threadIdx.x;
    if (i < n) { a[i] = 0; b[i] = 0; }
}

__global__ __launch_bounds__(256) void hist_kernel(
    const int* __restrict__ dst, int* __restrict__ deg, int E)
{
    int i = blockIdx.x * blockDim.x + threadIdx.x;
    if (i < E) atomicAdd(&deg[__ldg(dst + i)], 1);
}

__global__ __launch_bounds__(1024) void scan_kernel(
    const int* __restrict__ deg, int* __restrict__ rowStart)
{
    __shared__ int sums[1024];
    const int tid = threadIdx.x;
    const int CH  = (N_NODES + 1023) / 1024;
    const int base = tid * CH;
    int s = 0;
    for (int i = 0; i < CH; i++) {
        int idx = base + i;
        if (idx < N_NODES) s += deg[idx];
    }
    sums[tid] = s;
    __syncthreads();
    for (int off = 1; off < 1024; off <<= 1) {
        int v = (tid >= off) ? sums[tid - off] : 0;
        __syncthreads();
        sums[tid] += v;
        __syncthreads();
    }
    int run = sums[tid] - s;
    for (int i = 0; i < CH; i++) {
        int idx = base + i;
        if (idx < N_NODES) { rowStart[idx] = run; run += deg[idx]; }
    }
    if (tid == 1023) rowStart[N_NODES] = run;
}

__global__ __launch_bounds__(256) void scatter_kernel(
    const int* __restrict__ src, const int* __restrict__ dst,
    const int* __restrict__ rowStart, int* __restrict__ cursor,
    int* __restrict__ sortedSrc, int E)
{
    int i = blockIdx.x * blockDim.x + threadIdx.x;
    if (i >= E) return;
    int d = __ldg(dst + i);
    int pos = __ldg(rowStart + d) + atomicAdd(&cursor[d], 1);
    sortedSrc[pos] = __ldg(src + i);
}

// PvT scatter: carries (col, val) into row-sorted order
__global__ __launch_bounds__(256) void pvt_scatter_kernel(
    const int* __restrict__ prow, const int* __restrict__ pcol,
    const float* __restrict__ pval, const int* __restrict__ rowStart,
    int* __restrict__ cursor, int* __restrict__ colS,
    float* __restrict__ valS, int nnz)
{
    int i = blockIdx.x * blockDim.x + threadIdx.x;
    if (i >= nnz) return;
    int r = __ldg(prow + i);
    int pos = __ldg(rowStart + r) + atomicAdd(&cursor[r], 1);
    colS[pos] = __ldg(pcol + i);
    valS[pos] = __ldg(pval + i);
}

// ---------------------------------------------------------------------------
// Tensor-core GEMM: Y = half(relu(A[M,256] @ W[256,256] + bias)).
// ---------------------------------------------------------------------------
__device__ __forceinline__ void mma_16816(float c[4], const unsigned a[4],
                                          const unsigned b[2])
{
    asm volatile(
        "mma.sync.aligned.m16n8k16.row.col.f32.f16.f16.f32 "
        "{%0,%1,%2,%3}, {%4,%5,%6,%7}, {%8,%9}, {%0,%1,%2,%3};\n"
        : "+f"(c[0]), "+f"(c[1]), "+f"(c[2]), "+f"(c[3])
        : "r"(a[0]), "r"(a[1]), "r"(a[2]), "r"(a[3]), "r"(b[0]), "r"(b[1]));
}

template <bool A_FP32>
__global__ __launch_bounds__(256, 2) void gemm_mma(
    const void* __restrict__ Av, const __half* __restrict__ Wt,
    const float* __restrict__ bias, __half* __restrict__ Y, int rowOff)
{
    __shared__ __half As[128 * SP];
    __shared__ __half Bs[128 * SP];

    const int tid   = threadIdx.x;
    const int wid   = tid >> 5;
    const int lane  = tid & 31;
    const int gid   = lane >> 2;
    const int tig   = lane & 3;
    const int warp_m = wid & 3;
    const int warp_n = wid >> 2;
    const int rowBase = rowOff + blockIdx.y * 128;
    const int colBase = blockIdx.x * 128;

    float acc[2][8][4];
#pragma unroll
    for (int mf = 0; mf < 2; mf++)
#pragma unroll
        for (int nf = 0; nf < 8; nf++)
#pragma unroll
            for (int j = 0; j < 4; j++) acc[mf][nf][j] = 0.0f;

    for (int k0 = 0; k0 < FDIM; k0 += 32) {
#pragma unroll
        for (int i = 0; i < 2; i++) {
            int idx = tid + i * 256;
            int r   = idx >> 2;
            int cg  = idx & 3;
            int gr  = rowBase + r;
            uint4 va;
            if (A_FP32) {
                float4 f0 = make_float4(0.f, 0.f, 0.f, 0.f);
                float4 f1 = make_float4(0.f, 0.f, 0.f, 0.f);
                if (gr < N_NODES) {
                    const float* ap = (const float*)Av + (size_t)gr * FDIM + k0 + cg * 8;
                    f0 = *(const float4*)ap;
                    f1 = *(const float4*)(ap + 4);
                }
                __half2 h0 = __floats2half2_rn(f0.x, f0.y);
                __half2 h1 = __floats2half2_rn(f0.z, f0.w);
                __half2 h2 = __floats2half2_rn(f1.x, f1.y);
                __half2 h3 = __floats2half2_rn(f1.z, f1.w);
                va = make_uint4(*(unsigned*)&h0, *(unsigned*)&h1,
                                *(unsigned*)&h2, *(unsigned*)&h3);
            } else {
                va = make_uint4(0u, 0u, 0u, 0u);
                if (gr < N_NODES)
                    va = *(const uint4*)((const __half*)Av + (size_t)gr * FDIM + k0 + cg * 8);
            }
            *(uint4*)&As[r * SP + cg * 8] = va;
            uint4 vb = *(const uint4*)(Wt + (size_t)(colBase + r) * FDIM + k0 + cg * 8);
            *(uint4*)&Bs[r * SP + cg * 8] = vb;
        }
        __syncthreads();

#pragma unroll
        for (int ks = 0; ks < 2; ks++) {
            const int kk = ks * 16 + tig * 2;
            unsigned af[2][4];
#pragma unroll
            for (int mf = 0; mf < 2; mf++) {
                int r0 = warp_m * 32 + mf * 16 + gid;
                af[mf][0] = *(const unsigned*)&As[(r0    ) * SP + kk];
                af[mf][1] = *(const unsigned*)&As[(r0 + 8) * SP + kk];
                af[mf][2] = *(const unsigned*)&As[(r0    ) * SP + kk + 8];
                af[mf][3] = *(const unsigned*)&As[(r0 + 8) * SP + kk + 8];
            }
#pragma unroll
            for (int nf = 0; nf < 8; nf++) {
                int c0 = warp_n * 64 + nf * 8 + gid;
                unsigned bf[2];
                bf[0] = *(const unsigned*)&Bs[c0 * SP + kk];
                bf[1] = *(const unsigned*)&Bs[c0 * SP + kk + 8];
                mma_16816(acc[0][nf], af[0], bf);
                mma_16816(acc[1][nf], af[1], bf);
            }
        }
        __syncthreads();
    }

    float2 bv[8];
#pragma unroll
    for (int nf = 0; nf < 8; nf++)
        bv[nf] = *(const float2*)(bias + colBase + warp_n * 64 + nf * 8 + tig * 2);

#pragma unroll
    for (int mf = 0; mf < 2; mf++) {
        int gr0 = rowBase + warp_m * 32 + mf * 16 + gid;
        int gr1 = gr0 + 8;
#pragma unroll
        for (int nf = 0; nf < 8; nf++) {
            int col = colBase + warp_n * 64 + nf * 8 + tig * 2;
            if (gr0 < N_NODES) {
                __half2 h = __floats2half2_rn(
                    fmaxf(acc[mf][nf][0] + bv[nf].x, 0.f),
                    fmaxf(acc[mf][nf][1] + bv[nf].y, 0.f));
                *(__half2*)(Y + (size_t)gr0 * FDIM + col) = h;
            }
            if (gr1 < N_NODES) {
                __half2 h = __floats2half2_rn(
                    fmaxf(acc[mf][nf][2] + bv[nf].x, 0.f),
                    fmaxf(acc[mf][nf][3] + bv[nf].y, 0.f));
                *(__half2*)(Y + (size_t)gr1 * FDIM + col) = h;
            }
        }
    }
}

// ---------------------------------------------------------------------------
// FC via tensor cores: logits[N,40] = h2[N,256](fp16) @ WfcT + bfc (fp32 out).
// ---------------------------------------------------------------------------
__global__ __launch_bounds__(256, 2) void fc_mma(
    const __half* __restrict__ A, const __half* __restrict__ Wt,
    const float* __restrict__ bias, float* __restrict__ L)
{
    __shared__ __half As[128 * SP];
    __shared__ __half Bs[64 * SP];

    const int tid  = threadIdx.x;
    const int wid  = tid >> 5;
    const int lane = tid & 31;
    const int gid  = lane >> 2;
    const int tig  = lane & 3;
    const int rowBase = blockIdx.y * 128;

    float acc[8][4];
#pragma unroll
    for (int nf = 0; nf < 8; nf++)
#pragma unroll
        for (int j = 0; j < 4; j++) acc[nf][j] = 0.0f;

    for (int k0 = 0; k0 < FDIM; k0 += 32) {
#pragma unroll
        for (int i = 0; i < 2; i++) {
            int idx = tid + i * 256;
            int r   = idx >> 2;
            int cg  = idx & 3;
            int gr  = rowBase + r;
            uint4 va = make_uint4(0u, 0u, 0u, 0u);
            if (gr < N_NODES)
                va = *(const uint4*)(A + (size_t)gr * FDIM + k0 + cg * 8);
            *(uint4*)&As[r * SP + cg * 8] = va;
        }
        {
            int r  = tid >> 2;
            int cg = tid & 3;
            uint4 vb = *(const uint4*)(Wt + (size_t)r * FDIM + k0 + cg * 8);
            *(uint4*)&Bs[r * SP + cg * 8] = vb;
        }
        __syncthreads();

#pragma unroll
        for (int ks = 0; ks < 2; ks++) {
            const int kk = ks * 16 + tig * 2;
            unsigned af[4];
            int r0 = wid * 16 + gid;
            af[0] = *(const unsigned*)&As[(r0    ) * SP + kk];
            af[1] = *(const unsigned*)&As[(r0 + 8) * SP + kk];
            af[2] = *(const unsigned*)&As[(r0    ) * SP + kk + 8];
            af[3] = *(const unsigned*)&As[(r0 + 8) * SP + kk + 8];
#pragma unroll
            for (int nf = 0; nf < 8; nf++) {
                int c0 = nf * 8 + gid;
                unsigned bf[2];
                bf[0] = *(const unsigned*)&Bs[c0 * SP + kk];
                bf[1] = *(const unsigned*)&Bs[c0 * SP + kk + 8];
                mma_16816(acc[nf], af, bf);
            }
        }
        __syncthreads();
    }

#pragma unroll
    for (int nf = 0; nf < 8; nf++) {
        int c0 = nf * 8 + tig * 2;
        if (c0 >= NCLS) continue;
        float2 bv = *(const float2*)(bias + c0);
        int r0 = rowBase + wid * 16 + gid;
        int r1 = r0 + 8;
        if (r0 < N_NODES)
            *(float2*)(L + (size_t)r0 * NCLS + c0) =
                make_float2(acc[nf][0] + bv.x, acc[nf][1] + bv.y);
        if (r1 < N_NODES)
            *(float2*)(L + (size_t)r1 * NCLS + c0) =
                make_float2(acc[nf][2] + bv.x, acc[nf][3] + bv.y);
    }
}

// ---------------------------------------------------------------------------
// CSR gather aggregation (fp16 -> fp32 acc -> fp16), chunked by node range.
// ---------------------------------------------------------------------------
__device__ __forceinline__ void hacc8(float* acc, uint4 v)
{
    float2 f0 = __half22float2(*reinterpret_cast<__half2*>(&v.x));
    float2 f1 = __half22float2(*reinterpret_cast<__half2*>(&v.y));
    float2 f2 = __half22float2(*reinterpret_cast<__half2*>(&v.z));
    float2 f3 = __half22float2(*reinterpret_cast<__half2*>(&v.w));
    acc[0] += f0.x; acc[1] += f0.y;
    acc[2] += f1.x; acc[3] += f1.y;
    acc[4] += f2.x; acc[5] += f2.y;
    acc[6] += f3.x; acc[7] += f3.y;
}

__global__ __launch_bounds__(256) void aggregate_csr_h(
    const __half* __restrict__ Y, __half* __restrict__ H,
    const int* __restrict__ rowStart, const int* __restrict__ ssrc,
    int nodeOff, int nodeEnd)
{
    int node = nodeOff + blockIdx.x * 8 + (threadIdx.x >> 5);
    int lane = threadIdx.x & 31;
    if (node >= nodeEnd) return;

    const uint4* yb = (const uint4*)Y;
    float acc[8];
#pragma unroll
    for (int i = 0; i < 8; i++) acc[i] = 0.0f;

    hacc8(acc, __ldg(yb + (size_t)node * 32 + lane));   // self loop

    int e    = __ldg(rowStart + node);
    int eEnd = __ldg(rowStart + node + 1);

    for (; e + 4 <= eEnd; e += 4) {
        int s0 = __ldg(ssrc + e);
        int s1 = __ldg(ssrc + e + 1);
        int s2 = __ldg(ssrc + e + 2);
        int s3 = __ldg(ssrc + e + 3);
        uint4 v0 = __ldg(yb + (size_t)s0 * 32 + lane);
        uint4 v1 = __ldg(yb + (size_t)s1 * 32 + lane);
        uint4 v2 = __ldg(yb + (size_t)s2 * 32 + lane);
        uint4 v3 = __ldg(yb + (size_t)s3 * 32 + lane);
        hacc8(acc, v0); hacc8(acc, v1); hacc8(acc, v2); hacc8(acc, v3);
    }
    for (; e < eEnd; e++) {
        int s0 = __ldg(ssrc + e);
        hacc8(acc, __ldg(yb + (size_t)s0 * 32 + lane));
    }

    __half2 o0 = __floats2half2_rn(acc[0], acc[1]);
    __half2 o1 = __floats2half2_rn(acc[2], acc[3]);
    __half2 o2 = __floats2half2_rn(acc[4], acc[5]);
    __half2 o3 = __floats2half2_rn(acc[6], acc[7]);
    uint4 st;
    st.x = *(unsigned*)&o0; st.y = *(unsigned*)&o1;
    st.z = *(unsigned*)&o2; st.w = *(unsigned*)&o3;
    *(uint4*)(H + (size_t)node * FDIM + lane * 8) = st;
}

// ---------------------------------------------------------------------------
// Fused head: out[r] = log_softmax( sum_{nz in PvT row r} val * logits[col] ).
// One warp per output row. Empty rows give log_softmax(0) = -log(40).
// ---------------------------------------------------------------------------
__global__ __launch_bounds__(256) void head_kernel(
    const float* __restrict__ L, const int* __restrict__ prs,
    const int* __restrict__ pcolS, const float* __restrict__ pvalS,
    float* __restrict__ out)
{
    int row  = blockIdx.x * 8 + (threadIdx.x >> 5);
    int lane = threadIdx.x & 31;
    if (row >= N_NODES) return;

    float x0 = 0.0f, x1 = 0.0f;
    int e    = __ldg(prs + row);
    int eEnd = __ldg(prs + row + 1);
    for (; e < eEnd; e++) {
        int   c = __ldg(pcolS + e);
        float v = __ldg(pvalS + e);
        const float* lr = L + (size_t)c * NCLS;
        x0 = fmaf(v, __ldg(lr + lane), x0);
        if (lane < 8) x1 = fmaf(v, __ldg(lr + 32 + lane), x1);
    }

    float m = fmaxf(x0, (lane < 8) ? x1 : -INFINITY);
#pragma unroll
    for (int off = 16; off > 0; off >>= 1)
        m = fmaxf(m, __shfl_xor_sync(0xffffffffu, m, off));
    float s = __expf(x0 - m) + ((lane < 8) ? __expf(x1 - m) : 0.0f);
#pragma unroll
    for (int off = 16; off > 0; off >>= 1)
        s += __shfl_xor_sync(0xffffffffu, s, off);
    float ls = logf(s);
    float* o = out + (size_t)row * NCLS;
    o[lane] = x0 - m - ls;
    if (lane < 8) o[32 + lane] = x1 - m - ls;
}

// ---------------------------------------------------------------------------
extern "C" void kernel_launch(void* const* d_in, const int* in_sizes, int n_in,
                              void* d_out, int out_size)
{
    const float* x    = (const float*)d_in[0];
    const int*   esrc = (const int*)  d_in[1];
    const int*   edst = (const int*)  d_in[2];
    const int*   prow = (const int*)  d_in[3];
    const int*   pcol = (const int*)  d_in[4];
    const float* pval = (const float*)d_in[5];
    const float* w1   = (const float*)d_in[6];
    const float* b1   = (const float*)d_in[7];
    const float* w2   = (const float*)d_in[8];
    const float* b2   = (const float*)d_in[9];
    const float* wfc  = (const float*)d_in[10];
    const float* bfc  = (const float*)d_in[11];
    const int E   = in_sizes[1];
    const int nnz = in_sizes[3];

    __half *Y1h, *Y2h, *h1h, *h2h, *w1t, *w2t, *wfct;
    float *bfcp, *logits, *pvalS;
    int *ssrc, *rowStart, *deg, *cursor;
    int *pdeg, *pcursor, *prowStart, *pcolS;
    cudaGetSymbolAddress((void**)&Y1h,       g_Y1h);
    cudaGetSymbolAddress((void**)&Y2h,       g_Y2h);
    cudaGetSymbolAddress((void**)&h1h,       g_h1h);
    cudaGetSymbolAddress((void**)&h2h,       g_h2h);
    cudaGetSymbolAddress((void**)&w1t,       g_w1t);
    cudaGetSymbolAddress((void**)&w2t,       g_w2t);
    cudaGetSymbolAddress((void**)&wfct,      g_wfct);
    cudaGetSymbolAddress((void**)&bfcp,      g_bfcp);
    cudaGetSymbolAddress((void**)&logits,    g_logits);
    cudaGetSymbolAddress((void**)&ssrc,      g_sortedSrc);
    cudaGetSymbolAddress((void**)&rowStart,  g_rowStart);
    cudaGetSymbolAddress((void**)&deg,       g_deg);
    cudaGetSymbolAddress((void**)&cursor,    g_cursor);
    cudaGetSymbolAddress((void**)&pdeg,      g_pdeg);
    cudaGetSymbolAddress((void**)&pcursor,   g_pcursor);
    cudaGetSymbolAddress((void**)&prowStart, g_prowStart);
    cudaGetSymbolAddress((void**)&pcolS,     g_pcolS);
    cudaGetSymbolAddress((void**)&pvalS,     g_pvalS);

    static cudaStream_t side = nullptr, side2 = nullptr;
    static cudaEvent_t evFork = nullptr, evCSR = nullptr, evJoin = nullptr;
    static cudaEvent_t evPvt = nullptr;
    static cudaEvent_t evA[NCHUNK] = {};
    if (!side) {
        cudaStreamCreateWithFlags(&side,  cudaStreamNonBlocking);
        cudaStreamCreateWithFlags(&side2, cudaStreamNonBlocking);
        cudaEventCreateWithFlags(&evFork, cudaEventDisableTiming);
        cudaEventCreateWithFlags(&evCSR,  cudaEventDisableTiming);
        cudaEventCreateWithFlags(&evJoin, cudaEventDisableTiming);
        cudaEventCreateWithFlags(&evPvt,  cudaEventDisableTiming);
        for (int c = 0; c < NCHUNK; c++)
            cudaEventCreateWithFlags(&evA[c], cudaEventDisableTiming);
    }

    cudaEventRecord(evFork, 0);

    // --- side2: PvT CSR build (only consumed by head_kernel at the end) ---
    cudaStreamWaitEvent(side2, evFork, 0);
    zero2_i32<<<(N_NODES + 255) / 256, 256, 0, side2>>>(pdeg, pcursor, N_NODES);
    hist_kernel<<<(nnz + 255) / 256, 256, 0, side2>>>(prow, pdeg, nnz);
    scan_kernel<<<1, 1024, 0, side2>>>(pdeg, prowStart);
    pvt_scatter_kernel<<<(nnz + 255) / 256, 256, 0, side2>>>(
        prow, pcol, pval, prowStart, pcursor, pcolS, pvalS, nnz);
    cudaEventRecord(evPvt, side2);

    // --- side: edge CSR build + converts (round-9 shape) ---
    cudaStreamWaitEvent(side, evFork, 0);
    zero2_i32<<<(N_NODES + 255) / 256, 256, 0, side>>>(deg, cursor, N_NODES);
    hist_kernel<<<(E + 255) / 256, 256, 0, side>>>(edst, deg, E);
    scan_kernel<<<1, 1024, 0, side>>>(deg, rowStart);
    scatter_kernel<<<(E + 255) / 256, 256, 0, side>>>(esrc, edst, rowStart,
                                                      cursor, ssrc, E);
    cudaEventRecord(evCSR, side);
    wconv_kernel<<<FDIM, FDIM, 0, side>>>(w2, w2t);
    wfc_conv_kernel<<<NPAD, FDIM, 0, side>>>(wfc, wfct);
    bfc_pad_kernel<<<1, NPAD, 0, side>>>(bfc, bfcp);

    // --- main: W1 convert + conv1 GEMM (reads fp32 x directly) ---
    wconv_kernel<<<FDIM, FDIM>>>(w1, w1t);
    dim3 g1_grid(FDIM / 128, (N_NODES + 127) / 128);
    gemm_mma<true><<<g1_grid, 256>>>(x, w1t, b1, Y1h, 0);

    // --- A1 (main, chunked) pipelined with G2 (side, chunked) ---
    cudaStreamWaitEvent(0, evCSR, 0);
    for (int c = 0; c < NCHUNK; c++) {
        int n0 = c * CHUNK_ROWS;
        int n1 = min(N_NODES, n0 + CHUNK_ROWS);
        int nb = (n1 - n0 + 7) / 8;
        aggregate_csr_h<<<nb, 256>>>(Y1h, h1h, rowStart, ssrc, n0, n1);
        cudaEventRecord(evA[c], 0);
        cudaStreamWaitEvent(side, evA[c], 0);
        dim3 g2_grid(FDIM / 128, (n1 - n0 + 127) / 128);
        gemm_mma<false><<<g2_grid, 256, 0, side>>>(h1h, w2t, b2, Y2h, n0);
    }
    cudaEventRecord(evJoin, side);
    cudaStreamWaitEvent(0, evJoin, 0);

    // --- A2 + head (main, round-9 structure + fused head) ---
    aggregate_csr_h<<<(N_NODES + 7) / 8, 256>>>(Y2h, h2h, rowStart, ssrc,
                                                0, N_NODES);
    fc_mma<<<dim3(1, (N_NODES + 127) / 128), 256>>>(h2h, wfct, bfcp, logits);
    cudaStreamWaitEvent(0, evPvt, 0);
    head_kernel<<<(N_NODES + 7) / 8, 256>>>(logits, prowStart, pcolS, pvalS,
                                            (float*)d_out);
}